// round 7
// baseline (speedup 1.0000x reference)
#include <cuda_runtime.h>
#include <cstdint>

// CRF loss: mean_b( logZ_b - gold_b );  B=256, T=1024, C=64
// Scaled-domain forward: p_{t+1} = (E^T p_t) ∘ W_t / c_t,  logZ += log c_t.
// 512-thread blocks = 8 independent 64-thread batch groups -> 4 independent
// recursion chains per SMSP (latency overlap). Named barriers 1..8 per group.

#define BD 256
#define TD 1024
#define CD 64
#define GPB 8                    // groups (batches) per block
#define LOG2E 1.4426950408889634f
#define LN2   0.6931471805599453f

__device__ float g_partial[BD];

__device__ __forceinline__ float fast_exp2(float x) {
    float y; asm("ex2.approx.ftz.f32 %0, %1;" : "=f"(y) : "f"(x)); return y;
}
__device__ __forceinline__ float fast_log2(float x) {
    float y; asm("lg2.approx.ftz.f32 %0, %1;" : "=f"(y) : "f"(x)); return y;
}
__device__ __forceinline__ float fast_rcp(float x) {
    float y; asm("rcp.approx.ftz.f32 %0, %1;" : "=f"(y) : "f"(x)); return y;
}
__device__ __forceinline__ unsigned long long pack2(float lo, float hi) {
    unsigned long long r;
    asm("mov.b64 %0, {%1, %2};" : "=l"(r) : "f"(lo), "f"(hi)); return r;
}
__device__ __forceinline__ unsigned long long ffma2(unsigned long long a,
                                                    unsigned long long b,
                                                    unsigned long long c) {
    unsigned long long d;
    asm("fma.rn.f32x2 %0, %1, %2, %3;" : "=l"(d) : "l"(a), "l"(b), "l"(c));
    return d;
}
__device__ __forceinline__ float2 unpack2(unsigned long long v) {
    float2 f;
    asm("mov.b64 {%0, %1}, %2;" : "=f"(f.x), "=f"(f.y) : "l"(v)); return f;
}

// per-group barrier (64 threads = 2 warps), ids 1..GPB
#define GBAR(g) asm volatile("bar.sync %0, 64;" :: "r"((g) + 1) : "memory")

__global__ __launch_bounds__(GPB * CD)
void crf_forward_kernel(const float* __restrict__ emissions,
                        const float* __restrict__ transitions,
                        const float* __restrict__ start_t,
                        const float* __restrict__ end_t,
                        const int*   __restrict__ tags,
                        const float* __restrict__ mask)
{
    __shared__ __align__(16) float psh[GPB][2][CD];  // [group][buf][tag]
    __shared__ float swp[GPB][2];
    __shared__ float gred[GPB][2];
    __shared__ int   cred[GPB][2];

    const int g    = threadIdx.x >> 6;        // batch group 0..7
    const int j    = threadIdx.x & 63;        // tag owned by this thread
    const int w    = (threadIdx.x >> 5) & 1;  // warp within group
    const int lane = threadIdx.x & 31;
    const int b    = blockIdx.x * GPB + g;

    const float* em = emissions + (size_t)b * TD * CD;
    const int*   tg = tags      + (size_t)b * TD;
    const float* mk = mask      + (size_t)b * TD;

    // ---- E column j, packed in pairs: Ecp[k] = {E[2k][j], E[2k+1][j]} ----
    unsigned long long Ecp[CD / 2];
    #pragma unroll
    for (int k = 0; k < CD / 2; k++) {
        float e0 = fast_exp2(transitions[(2 * k)     * CD + j] * LOG2E);
        float e1 = fast_exp2(transitions[(2 * k + 1) * CD + j] * LOG2E);
        Ecp[k] = pack2(e0, e1);
    }

    // ---- gold score (parallel over t within the group) ----
    float gp  = 0.f;
    int   cnt = 0;
    for (int t = j; t < TD; t += CD) {
        float m = mk[t];
        cnt += (int)m;
        if (t >= 1) {
            int tc = tg[t], tp = tg[t - 1];
            gp += m * (em[t * CD + tc] + transitions[tp * CD + tc]);
        }
    }
    #pragma unroll
    for (int off = 16; off; off >>= 1) {
        gp  += __shfl_xor_sync(0xffffffffu, gp,  off);
        cnt += __shfl_xor_sync(0xffffffffu, cnt, off);
    }
    if (lane == 0) { gred[g][w] = gp; cred[g][w] = cnt; }

    // ---- forward init (t = 0), linear domain ----
    float myp = fast_exp2((start_t[j] + em[j]) * LOG2E);
    psh[g][0][j] = myp;

    // ---- prefetch ring: W = exp(emit), mask — 8 deep ----
    float Wr[8], mr[8];
    #pragma unroll
    for (int t0 = 1; t0 <= 8; t0++) {
        Wr[t0 & 7] = fast_exp2(em[t0 * CD + j] * LOG2E);
        mr[t0 & 7] = mk[t0];
    }

    GBAR(g);   // psh[g][0], gred/cred visible within group

    float gold = 0.f;
    if (j == 0) {
        int seqlen  = cred[g][0] + cred[g][1];
        int lastidx = seqlen - 1; if (lastidx < 0) lastidx = 0;
        int t0 = tg[0], tl = tg[lastidx];
        gold = gred[g][0] + gred[g][1] + start_t[t0] + em[t0] + end_t[tl];
    }

    // ---- forward recursion: one named barrier per step ----
    float logAcc = 0.f;
    int   cur    = 0;

    #pragma unroll 8
    for (int t = 1; t < TD; t++) {
        const int   slot = t & 7;
        const float W    = Wr[slot];
        const float mt   = mr[slot];

        const int tp = t + 8;                    // refill ring (off-chain)
        if (tp < TD) {
            Wr[slot] = fast_exp2(em[tp * CD + j] * LOG2E);
            mr[slot] = mk[tp];
        }

        const float* pc = psh[g][cur];
        const float  c  = pc[0];                 // broadcast LDS (normalizer)
        const float  r  = fast_rcp(c);
        logAcc += fast_log2(c);

        unsigned long long a0 = 0ull, a1 = 0ull, a2 = 0ull, a3 = 0ull;
        #pragma unroll
        for (int i = 0; i < CD; i += 8) {
            ulonglong2 qa = *(const ulonglong2*)&pc[i];      // p[i..i+3]
            ulonglong2 qb = *(const ulonglong2*)&pc[i + 4];  // p[i+4..i+7]
            a0 = ffma2(qa.x, Ecp[i / 2 + 0], a0);
            a1 = ffma2(qa.y, Ecp[i / 2 + 1], a1);
            a2 = ffma2(qb.x, Ecp[i / 2 + 2], a2);
            a3 = ffma2(qb.y, Ecp[i / 2 + 3], a3);
        }
        float2 f0 = unpack2(a0), f1 = unpack2(a1);
        float2 f2 = unpack2(a2), f3 = unpack2(a3);
        const float s  = ((f0.x + f0.y) + (f1.x + f1.y))
                       + ((f2.x + f2.y) + (f3.x + f3.y));
        const float pn = s * W * r;
        // masked step: p scaled by r (cancels logAcc += log2 c)
        myp = (mt > 0.f) ? pn : myp * r;
        psh[g][cur ^ 1][j] = myp;
        GBAR(g);
        cur ^= 1;
    }

    // ---- final: logZ = LN2 * (logAcc + log2(sum_j p_j * exp(end_j))) ----
    float v = myp * fast_exp2(end_t[j] * LOG2E);
    #pragma unroll
    for (int off = 16; off; off >>= 1)
        v += __shfl_xor_sync(0xffffffffu, v, off);
    if (lane == 0) swp[g][w] = v;
    GBAR(g);

    if (j == 0) {
        float fwd = (logAcc + fast_log2(swp[g][0] + swp[g][1])) * LN2;
        g_partial[b] = fwd - gold;
    }
}

__global__ void crf_reduce_kernel(float* __restrict__ out)
{
    const int j = threadIdx.x;     // 256 threads
    float v = g_partial[j];
    __shared__ float sm[8];
    #pragma unroll
    for (int off = 16; off; off >>= 1)
        v += __shfl_xor_sync(0xffffffffu, v, off);
    if ((j & 31) == 0) sm[j >> 5] = v;
    __syncthreads();
    if (j < 8) {
        v = sm[j];
        #pragma unroll
        for (int off = 4; off; off >>= 1)
            v += __shfl_xor_sync(0x000000ffu, v, off);
        if (j == 0) out[0] = v * (1.0f / BD);
    }
}

extern "C" void kernel_launch(void* const* d_in, const int* in_sizes, int n_in,
                              void* d_out, int out_size)
{
    const float* emissions   = (const float*)d_in[0];
    const float* transitions = (const float*)d_in[1];
    const float* start_t     = (const float*)d_in[2];
    const float* end_t       = (const float*)d_in[3];
    const int*   tags        = (const int*)  d_in[4];
    const float* mask        = (const float*)d_in[5];
    float* out = (float*)d_out;

    crf_forward_kernel<<<BD / GPB, GPB * CD>>>(emissions, transitions, start_t, end_t, tags, mask);
    crf_reduce_kernel<<<1, BD>>>(out);
}

// round 10
// speedup vs baseline: 2.0951x; 2.0951x over previous
#include <cuda_runtime.h>
#include <cstdint>

// CRF loss: mean_b( logZ_b - gold_b );  B=256, T=1024, C=64
// Scaled-domain forward: p_{t+1} = (E^T p_t) ∘ W_t / c_t,  logZ += log2 c_t.
// ONE WARP PER BATCH CHAIN (2 tags/thread): p-exchange is intra-warp
// (STS -> __syncwarp -> LDS), no named barriers. 128-thread blocks = 4 chains,
// one per SMSP; grid 64 -> every chain alone on its SMSP. Reduction fused.

#define BD 256
#define TD 1024
#define CD 64
#define LOG2E 1.4426950408889634f
#define LN2   0.6931471805599453f

__device__ float        g_partial[BD];
__device__ unsigned int g_done = 0;

__device__ __forceinline__ float fast_exp2(float x) {
    float y; asm("ex2.approx.ftz.f32 %0, %1;" : "=f"(y) : "f"(x)); return y;
}
__device__ __forceinline__ float fast_log2(float x) {
    float y; asm("lg2.approx.ftz.f32 %0, %1;" : "=f"(y) : "f"(x)); return y;
}
__device__ __forceinline__ float fast_rcp(float x) {
    float y; asm("rcp.approx.ftz.f32 %0, %1;" : "=f"(y) : "f"(x)); return y;
}
__device__ __forceinline__ unsigned long long pack2(float lo, float hi) {
    unsigned long long r;
    asm("mov.b64 %0, {%1, %2};" : "=l"(r) : "f"(lo), "f"(hi)); return r;
}
__device__ __forceinline__ unsigned long long ffma2(unsigned long long a,
                                                    unsigned long long b,
                                                    unsigned long long c) {
    unsigned long long d;
    asm("fma.rn.f32x2 %0, %1, %2, %3;" : "=l"(d) : "l"(a), "l"(b), "l"(c));
    return d;
}
__device__ __forceinline__ float2 unpack2(unsigned long long v) {
    float2 f;
    asm("mov.b64 {%0, %1}, %2;" : "=f"(f.x), "=f"(f.y) : "l"(v)); return f;
}

// One forward step for tags (j0, j1) of chain w. Indices must be compile-time.
#define STEP_BODY(T_, SLOT_)                                                   \
    {                                                                          \
        const int   t_   = (T_);                                               \
        const float W0   = Wr0[(SLOT_)];                                       \
        const float W1   = Wr1[(SLOT_)];                                       \
        const float mt   = mr[(SLOT_)];                                        \
        const int   tpf  = t_ + 8;                                             \
        if (tpf < TD) {                                                        \
            Wr0[(SLOT_)] = fast_exp2(em[tpf * CD + j0] * LOG2E);               \
            Wr1[(SLOT_)] = fast_exp2(em[tpf * CD + j1] * LOG2E);               \
            mr[(SLOT_)]  = mk[tpf];                                            \
        }                                                                      \
        const float* pc = psh[w][cur];                                         \
        const float  c  = pc[0];                                               \
        const float  r  = fast_rcp(c);                                         \
        logAcc += fast_log2(c);                                                \
        const float W0r = W0 * r, W1r = W1 * r;                                \
        unsigned long long a0 = 0ull, a1 = 0ull, a2 = 0ull, a3 = 0ull;         \
        unsigned long long b0 = 0ull, b1 = 0ull, b2 = 0ull, b3 = 0ull;         \
        _Pragma("unroll")                                                      \
        for (int i = 0; i < CD; i += 8) {                                      \
            ulonglong2 qa = *(const ulonglong2*)&pc[i];                        \
            ulonglong2 qb = *(const ulonglong2*)&pc[i + 4];                    \
            a0 = ffma2(qa.x, E0p[i / 2 + 0], a0);                              \
            b0 = ffma2(qa.x, E1p[i / 2 + 0], b0);                              \
            a1 = ffma2(qa.y, E0p[i / 2 + 1], a1);                              \
            b1 = ffma2(qa.y, E1p[i / 2 + 1], b1);                              \
            a2 = ffma2(qb.x, E0p[i / 2 + 2], a2);                              \
            b2 = ffma2(qb.x, E1p[i / 2 + 2], b2);                              \
            a3 = ffma2(qb.y, E0p[i / 2 + 3], a3);                              \
            b3 = ffma2(qb.y, E1p[i / 2 + 3], b3);                              \
        }                                                                      \
        float2 fa0 = unpack2(a0), fa1 = unpack2(a1);                           \
        float2 fa2 = unpack2(a2), fa3 = unpack2(a3);                           \
        float2 fb0 = unpack2(b0), fb1 = unpack2(b1);                           \
        float2 fb2 = unpack2(b2), fb3 = unpack2(b3);                           \
        const float s0 = ((fa0.x + fa0.y) + (fa1.x + fa1.y))                   \
                       + ((fa2.x + fa2.y) + (fa3.x + fa3.y));                  \
        const float s1 = ((fb0.x + fb0.y) + (fb1.x + fb1.y))                   \
                       + ((fb2.x + fb2.y) + (fb3.x + fb3.y));                  \
        const float p0n = s0 * W0r, p1n = s1 * W1r;                            \
        myp0 = (mt > 0.f) ? p0n : myp0 * r;                                    \
        myp1 = (mt > 0.f) ? p1n : myp1 * r;                                    \
        float* pn_ = psh[w][cur ^ 1];                                          \
        pn_[j0] = myp0;                                                        \
        pn_[j1] = myp1;                                                        \
        __syncwarp();                                                          \
        cur ^= 1;                                                              \
    }

__global__ __launch_bounds__(128)
void crf_fused_kernel(const float* __restrict__ emissions,
                      const float* __restrict__ transitions,
                      const float* __restrict__ start_t,
                      const float* __restrict__ end_t,
                      const int*   __restrict__ tags,
                      const float* __restrict__ mask,
                      float*       __restrict__ out)
{
    __shared__ __align__(16) float psh[4][2][CD];  // [chain][buf][tag]
    __shared__ float        rsm[4];
    __shared__ unsigned int last_flag;

    const int w    = threadIdx.x >> 5;    // chain within block (0..3)
    const int lane = threadIdx.x & 31;
    const int b    = blockIdx.x * 4 + w;  // batch index
    const int j0   = lane;
    const int j1   = lane + 32;

    const float* em = emissions + (size_t)b * TD * CD;
    const int*   tg = tags      + (size_t)b * TD;
    const float* mk = mask      + (size_t)b * TD;

    // ---- packed E columns: E?p[k] = {exp(T[2k][j?]), exp(T[2k+1][j?])} ----
    unsigned long long E0p[CD / 2], E1p[CD / 2];
    #pragma unroll
    for (int k = 0; k < CD / 2; k++) {
        const float* r0 = transitions + (2 * k)     * CD;
        const float* r1 = transitions + (2 * k + 1) * CD;
        E0p[k] = pack2(fast_exp2(r0[j0] * LOG2E), fast_exp2(r1[j0] * LOG2E));
        E1p[k] = pack2(fast_exp2(r0[j1] * LOG2E), fast_exp2(r1[j1] * LOG2E));
    }

    // ---- gold score (32 threads stride T) ----
    float gp  = 0.f;
    int   cnt = 0;
    for (int t = lane; t < TD; t += 32) {
        float m = mk[t];
        cnt += (int)m;
        if (t >= 1) {
            int tc = tg[t], tp = tg[t - 1];
            gp += m * (em[t * CD + tc] + transitions[tp * CD + tc]);
        }
    }
    #pragma unroll
    for (int off = 16; off; off >>= 1) {
        gp  += __shfl_xor_sync(0xffffffffu, gp,  off);
        cnt += __shfl_xor_sync(0xffffffffu, cnt, off);
    }
    int lastidx = cnt - 1; if (lastidx < 0) lastidx = 0;
    const int tfirst = tg[0], tlast = tg[lastidx];              // broadcast LDG
    const float gold = gp + start_t[tfirst] + em[tfirst] + end_t[tlast];

    // ---- init (t = 0), linear domain ----
    float myp0 = fast_exp2((start_t[j0] + em[j0]) * LOG2E);
    float myp1 = fast_exp2((start_t[j1] + em[j1]) * LOG2E);
    psh[w][0][j0] = myp0;
    psh[w][0][j1] = myp1;

    // ---- prefetch ring (8 deep): W = exp(emit), mask ----
    float Wr0[8], Wr1[8], mr[8];
    #pragma unroll
    for (int t0 = 1; t0 <= 8; t0++) {
        Wr0[t0 & 7] = fast_exp2(em[t0 * CD + j0] * LOG2E);
        Wr1[t0 & 7] = fast_exp2(em[t0 * CD + j1] * LOG2E);
        mr[t0 & 7]  = mk[t0];
    }
    __syncwarp();

    // ---- recursion: t = 1..1016 in 127 chunks of 8, then 1017..1023 peeled.
    // slot = t & 7 is compile-time constant in every expansion.
    float logAcc = 0.f;
    int   cur    = 0;

    for (int tb = 1; tb + 7 < TD; tb += 8) {   // tb = 1, 9, ..., 1009
        STEP_BODY(tb + 0, 1) STEP_BODY(tb + 1, 2) STEP_BODY(tb + 2, 3)
        STEP_BODY(tb + 3, 4) STEP_BODY(tb + 4, 5) STEP_BODY(tb + 5, 6)
        STEP_BODY(tb + 6, 7) STEP_BODY(tb + 7, 0)
    }
    // t = 1017..1023  (slots 1..7)
    STEP_BODY(1017, 1) STEP_BODY(1018, 2) STEP_BODY(1019, 3) STEP_BODY(1020, 4)
    STEP_BODY(1021, 5) STEP_BODY(1022, 6) STEP_BODY(1023, 7)

    // ---- final: logZ = LN2 * (logAcc + log2(sum_j p_j * exp(end_j))) ----
    float v = myp0 * fast_exp2(end_t[j0] * LOG2E)
            + myp1 * fast_exp2(end_t[j1] * LOG2E);
    #pragma unroll
    for (int off = 16; off; off >>= 1)
        v += __shfl_xor_sync(0xffffffffu, v, off);

    if (lane == 0)
        g_partial[b] = (logAcc + fast_log2(v)) * LN2 - gold;

    // ---- fused deterministic mean reduction (last block) ----
    __syncthreads();                       // all 4 chains' g_partial writes done
    if (threadIdx.x == 0) {
        __threadfence();                   // publish this block's writes
        unsigned int tk = atomicAdd(&g_done, 1u);
        last_flag = (tk == gridDim.x - 1) ? 1u : 0u;
    }
    __syncthreads();

    if (last_flag) {
        __threadfence();                   // acquire all blocks' writes
        float s = g_partial[threadIdx.x] + g_partial[threadIdx.x + 128];
        #pragma unroll
        for (int off = 16; off; off >>= 1)
            s += __shfl_xor_sync(0xffffffffu, s, off);
        if (lane == 0) rsm[w] = s;
        __syncthreads();
        if (threadIdx.x == 0) {
            out[0] = (rsm[0] + rsm[1] + rsm[2] + rsm[3]) * (1.0f / BD);
            g_done = 0;                    // reset for next graph replay
        }
    }
}

extern "C" void kernel_launch(void* const* d_in, const int* in_sizes, int n_in,
                              void* d_out, int out_size)
{
    const float* emissions   = (const float*)d_in[0];
    const float* transitions = (const float*)d_in[1];
    const float* start_t     = (const float*)d_in[2];
    const float* end_t       = (const float*)d_in[3];
    const int*   tags        = (const int*)  d_in[4];
    const float* mask        = (const float*)d_in[5];
    float* out = (float*)d_out;

    crf_fused_kernel<<<BD / 4, 128>>>(emissions, transitions, start_t, end_t,
                                      tags, mask, out);
}